// round 15
// baseline (speedup 1.0000x reference)
#include <cuda_runtime.h>
#include <cuda_bf16.h>
#include <stdint.h>

#define N_NODES 8192
#define D 128
#define K0 4096
#define K1 2048
#define K2 1024

// GEMM tile config: 128x128 CTA tile, BK=32, 3-stage cp.async pipeline,
// XOR-swizzled smem (64B rows, granule' = g ^ ((row>>1)&3)) -> no padding.
#define BM 128
#define BK 32
#define TILE_B (128 * 64)                // 8192 bytes per tile plane
#define STAGE_B (4 * TILE_B)             // Ah, Al, Bh, Bl = 32 KB
#define NSTAGE 3
#define GEMM_DYN (NSTAGE * STAGE_B + 256)

#define SORT_TILE 2048
#define GH_ROWS 8                        // rows per gatherH block (double-buffered)
#define GH_THR 1024

// ---------------- scratch (static __device__ arrays; no allocs) ----------------
__device__ __align__(256) float               g_score[N_NODES];
__device__ __align__(256) unsigned long long  g_key[N_NODES];
__device__ __align__(256) int                 g_perm0[K0];
__device__ __align__(256) int                 g_perm1[K1];
__device__ __align__(256) int                 g_perm2[K2];
__device__ __align__(256) int                 g_inv0[N_NODES];
__device__ __align__(256) int                 g_inv1[K0];
__device__ __align__(256) int                 g_inv2[K1];
__device__ __align__(256) float               g_xA[N_NODES * D];
__device__ __align__(256) float               g_xs1[K0 * D];
__device__ __align__(256) float               g_xs2[K1 * D];
__device__ __align__(256) __nv_bfloat16       g_Hg0h[(size_t)K0 * K0];
__device__ __align__(256) __nv_bfloat16       g_Hg0l[(size_t)K0 * K0];
__device__ __align__(256) __nv_bfloat16       g_Hg1h[(size_t)K1 * K1];
__device__ __align__(256) __nv_bfloat16       g_Hg1l[(size_t)K1 * K1];
__device__ __align__(256) __nv_bfloat16       g_Hg2h[(size_t)K2 * K2];
__device__ __align__(256) __nv_bfloat16       g_Hg2l[(size_t)K2 * K2];
__device__ __align__(256) float               g_part[4 * 1024 * 1024];
__device__ __align__(256) __nv_bfloat16       g_yth[D * N_NODES];
__device__ __align__(256) __nv_bfloat16       g_ytl[D * N_NODES];

// ---------------- PTX helpers ----------------
__device__ __forceinline__ uint32_t smem_u32(const void* p) {
    uint32_t a;
    asm("{ .reg .u64 t; cvta.to.shared.u64 t, %1; cvt.u32.u64 %0, t; }" : "=r"(a) : "l"(p));
    return a;
}
__device__ __forceinline__ void cpasync16(uint32_t dst, const void* src) {
    asm volatile("cp.async.cg.shared.global [%0], [%1], 16;" :: "r"(dst), "l"(src));
}
__device__ __forceinline__ void ldsm4(uint32_t* r, uint32_t a) {
    asm volatile("ldmatrix.sync.aligned.m8n8.x4.shared.b16 {%0,%1,%2,%3}, [%4];"
                 : "=r"(r[0]), "=r"(r[1]), "=r"(r[2]), "=r"(r[3]) : "r"(a));
}
__device__ __forceinline__ void mma_bf16(float* c, const uint32_t* a, uint32_t b0, uint32_t b1) {
    asm volatile("mma.sync.aligned.m16n8k16.row.col.f32.bf16.bf16.f32 "
                 "{%0,%1,%2,%3}, {%4,%5,%6,%7}, {%8,%9}, {%0,%1,%2,%3};"
                 : "+f"(c[0]), "+f"(c[1]), "+f"(c[2]), "+f"(c[3])
                 : "r"(a[0]), "r"(a[1]), "r"(a[2]), "r"(a[3]), "r"(b0), "r"(b1));
}
__device__ __forceinline__ uint32_t pack_bf16x2(float a, float b) {
    __nv_bfloat162 t = __floats2bfloat162_rn(a, b);
    return *reinterpret_cast<uint32_t*>(&t);
}
__device__ __forceinline__ unsigned long long score_to_key(float s, int row) {
    unsigned int b = __float_as_uint(s);
    b ^= (b & 0x80000000u) ? 0xFFFFFFFFu : 0x80000000u;
    unsigned int desc = ~b;
    return (((unsigned long long)desc) << 32) | (unsigned int)row;
}
__device__ __forceinline__ uint32_t swz(uint32_t row, uint32_t gran) {
    return row * 64u + ((gran ^ ((row >> 1) & 3u)) * 16u);
}

// ---------------- score + sort key (also resets inv) ----------------
__global__ void score_key_kernel(const float* __restrict__ x, const float* __restrict__ w,
                                 float* __restrict__ score, unsigned long long* __restrict__ key,
                                 int* __restrict__ inv, int n) {
    int warp = threadIdx.x >> 5, lane = threadIdx.x & 31;
    int row = blockIdx.x * (blockDim.x >> 5) + warp;
    if (row >= n) return;
    float4 xv = reinterpret_cast<const float4*>(x + (size_t)row * D)[lane];
    float4 wv = reinterpret_cast<const float4*>(w)[lane];
    float d  = xv.x * wv.x + xv.y * wv.y + xv.z * wv.z + xv.w * wv.w;
    float ww = wv.x * wv.x + wv.y * wv.y + wv.z * wv.z + wv.w * wv.w;
    #pragma unroll
    for (int o = 16; o; o >>= 1) {
        d  += __shfl_xor_sync(0xffffffffu, d, o);
        ww += __shfl_xor_sync(0xffffffffu, ww, o);
    }
    if (lane == 0) {
        float s = tanhf(d / sqrtf(ww));
        score[row] = s;
        key[row] = score_to_key(s, row);
        inv[row] = -1;
    }
}

// ---------------- tiled bitonic sort (R9 proven structure) ----------------
__global__ void sort_local(unsigned long long* __restrict__ key) {
    __shared__ unsigned long long s[SORT_TILE];
    int tid = threadIdx.x;
    int base = blockIdx.x * SORT_TILE;
    s[tid] = key[base + tid];
    s[tid + 1024] = key[base + tid + 1024];
    __syncthreads();
    for (int ksz = 2; ksz <= SORT_TILE; ksz <<= 1) {
        for (int j = ksz >> 1; j > 0; j >>= 1) {
            int i = ((tid & ~(j - 1)) << 1) | (tid & (j - 1));
            int x = i | j;
            bool up = (((base + i) & ksz) == 0);
            unsigned long long a = s[i], b = s[x];
            if ((a > b) == up) { s[i] = b; s[x] = a; }
            if (j > 32 || j == 1) __syncthreads(); else __syncwarp();
        }
    }
    key[base + tid] = s[tid];
    key[base + tid + 1024] = s[tid + 1024];
}

__global__ void lmerge(unsigned long long* __restrict__ key, int ksz) {
    __shared__ unsigned long long s[SORT_TILE];
    int tid = threadIdx.x;
    int base = blockIdx.x * SORT_TILE;
    s[tid] = key[base + tid];
    s[tid + 1024] = key[base + tid + 1024];
    __syncthreads();
    for (int j = SORT_TILE >> 1; j > 0; j >>= 1) {
        int i = ((tid & ~(j - 1)) << 1) | (tid & (j - 1));
        int x = i | j;
        bool up = (((base + i) & ksz) == 0);
        unsigned long long a = s[i], b = s[x];
        if ((a > b) == up) { s[i] = b; s[x] = a; }
        if (j > 32 || j == 1) __syncthreads(); else __syncwarp();
    }
    key[base + tid] = s[tid];
    key[base + tid + 1024] = s[tid + 1024];
}

__global__ void gmerge(unsigned long long* __restrict__ key, int ksz, int j) {
    int p = blockIdx.x * blockDim.x + threadIdx.x;
    int i = ((p & ~(j - 1)) << 1) | (p & (j - 1));
    int x = i | j;
    bool up = ((i & ksz) == 0);
    unsigned long long a = key[i], b = key[x];
    if ((a > b) == up) { key[i] = b; key[x] = a; }
}

__global__ void gmerge2_8192(unsigned long long* __restrict__ key) {
    int q = blockIdx.x * blockDim.x + threadIdx.x;  // 0..2047
    unsigned long long a0 = key[q], a1 = key[q + 2048], a2 = key[q + 4096], a3 = key[q + 6144];
    unsigned long long t;
    if (a0 > a2) { t = a0; a0 = a2; a2 = t; }
    if (a1 > a3) { t = a1; a1 = a3; a3 = t; }
    if (a0 > a1) { t = a0; a0 = a1; a1 = t; }
    if (a2 > a3) { t = a2; a2 = a3; a3 = t; }
    key[q] = a0; key[q + 2048] = a1; key[q + 4096] = a2; key[q + 6144] = a3;
}

static void run_sort(unsigned long long* key, int n) {
    sort_local<<<n / SORT_TILE, 1024>>>(key);
    if (n >= 4096) {
        gmerge<<<n / 512, 256>>>(key, 4096, 2048);
        lmerge<<<n / SORT_TILE, 1024>>>(key, 4096);
    }
    if (n >= 8192) {
        gmerge2_8192<<<8, 256>>>(key);
        lmerge<<<n / SORT_TILE, 1024>>>(key, 8192);
    }
}

// ---------------- fused DOWN: gather+gate 16 rows, emit perm/inv, compute Yt planes ----------------
// Identical arithmetic to gather_gate followed by xw_trans: xs = x[p]*score[p]; Yt = (xs@W + b)^T.
__global__ void gather_xw_kernel(const float* __restrict__ xin,
                                 const unsigned long long* __restrict__ key,
                                 const float* __restrict__ score,
                                 const float* __restrict__ W, const float* __restrict__ b,
                                 int* __restrict__ perm, int* __restrict__ inv,
                                 __nv_bfloat16* __restrict__ Yh, __nv_bfloat16* __restrict__ Yl,
                                 int n_sel) {
    __shared__ float xs[16][D];
    __shared__ int   ps[16];
    int r0 = blockIdx.x * 16;
    int tid = threadIdx.x;  // 128
    if (tid < 16) {
        int i = r0 + tid;
        int p = (int)(key[i] & 0xffffffffu);
        ps[tid] = p;
        perm[i] = p;
        inv[p] = i;
    }
    __syncthreads();
    #pragma unroll
    for (int r = 0; r < 16; r++) {
        int p = ps[r];
        xs[r][tid] = xin[(size_t)p * D + tid] * score[p];
    }
    __syncthreads();
    float bv = b[tid];
    float acc[16];
    #pragma unroll
    for (int r = 0; r < 16; r++) acc[r] = bv;
    #pragma unroll 4
    for (int kk = 0; kk < D; kk++) {
        float wv = W[kk * D + tid];
        #pragma unroll
        for (int r = 0; r < 16; r++) acc[r] += xs[r][kk] * wv;
    }
    #pragma unroll
    for (int r = 0; r < 16; r++) {
        float v = acc[r];
        __nv_bfloat16 h = __float2bfloat16(v);
        Yh[(size_t)tid * n_sel + r0 + r] = h;
        Yl[(size_t)tid * n_sel + r0 + r] = __float2bfloat16(v - __bfloat162float(h));
    }
}

// ---------------- H[perm][:,perm] -> bf16 hi/lo planes, cp.async double-buffered ----------------
__global__ void gatherH_pipe(const float* __restrict__ H, const int* __restrict__ perm,
                             __nv_bfloat16* __restrict__ Hh, __nv_bfloat16* __restrict__ Hl,
                             int k, int rowW) {
    extern __shared__ float sm[];
    float* buf0 = sm;
    float* buf1 = sm + rowW;
    int* ps = (int*)(sm + 2 * rowW);
    const int tid = threadIdx.x;            // GH_THR
    const int i0 = blockIdx.x * GH_ROWS;
    const int nch = rowW / 4;                // 16B chunks per row

    for (int j = tid; j < k; j += GH_THR) ps[j] = __ldg(&perm[j]);

    // prologue: stage row 0
    {
        int pi = __ldg(&perm[i0]);
        const char* src = (const char*)(H + (size_t)pi * N_NODES);
        uint32_t dst = smem_u32(buf0);
        for (int c = tid; c < nch; c += GH_THR) cpasync16(dst + c * 16u, src + (size_t)c * 16);
        asm volatile("cp.async.commit_group;");
    }

    for (int r = 0; r < GH_ROWS; r++) {
        asm volatile("cp.async.wait_group 0;" ::: "memory");
        __syncthreads();    // row r visible; all threads done gathering row r-1 (frees alt buffer)
        if (r + 1 < GH_ROWS) {
            int pi = __ldg(&perm[i0 + r + 1]);
            const char* src = (const char*)(H + (size_t)pi * N_NODES);
            uint32_t dst = smem_u32(((r + 1) & 1) ? buf1 : buf0);
            for (int c = tid; c < nch; c += GH_THR) cpasync16(dst + c * 16u, src + (size_t)c * 16);
            asm volatile("cp.async.commit_group;");
        }
        const float* rowf = (r & 1) ? buf1 : buf0;
        int i = i0 + r;
        __nv_bfloat16* dh = Hh + (size_t)i * k;
        __nv_bfloat16* dl = Hl + (size_t)i * k;
        for (int j0 = tid * 8; j0 < k; j0 += GH_THR * 8) {
            uint32_t hv[4], lv[4];
            #pragma unroll
            for (int q = 0; q < 4; q++) {
                float v0 = rowf[ps[j0 + 2 * q]];
                float v1 = rowf[ps[j0 + 2 * q + 1]];
                float h0 = __bfloat162float(__float2bfloat16(v0));
                float h1 = __bfloat162float(__float2bfloat16(v1));
                hv[q] = pack_bf16x2(v0, v1);
                lv[q] = pack_bf16x2(v0 - h0, v1 - h1);
            }
            *reinterpret_cast<uint4*>(dh + j0) = make_uint4(hv[0], hv[1], hv[2], hv[3]);
            *reinterpret_cast<uint4*>(dl + j0) = make_uint4(lv[0], lv[1], lv[2], lv[3]);
        }
    }
}

// ---------------- Yt = (X @ W + b)^T as bf16 hi/lo planes [128 x n] ----------------
__global__ void xw_trans_kernel(const float* __restrict__ X, const float* __restrict__ W,
                                const float* __restrict__ b,
                                __nv_bfloat16* __restrict__ Yh, __nv_bfloat16* __restrict__ Yl,
                                int n) {
    __shared__ float xs[16][D];
    int r0 = blockIdx.x * 16;
    int tid = threadIdx.x;
    #pragma unroll
    for (int r = 0; r < 16; r++) xs[r][tid] = X[(size_t)(r0 + r) * D + tid];
    __syncthreads();
    float bv = b[tid];
    float acc[16];
    #pragma unroll
    for (int r = 0; r < 16; r++) acc[r] = bv;
    #pragma unroll 4
    for (int kk = 0; kk < D; kk++) {
        float wv = W[kk * D + tid];
        #pragma unroll
        for (int r = 0; r < 16; r++) acc[r] += xs[r][kk] * wv;
    }
    #pragma unroll
    for (int r = 0; r < 16; r++) {
        float v = acc[r];
        __nv_bfloat16 h = __float2bfloat16(v);
        Yh[(size_t)tid * n + r0 + r] = h;
        Yl[(size_t)tid * n + r0 + r] = __float2bfloat16(v - __bfloat162float(h));
    }
}

// ---------------- mma.sync bf16 3-chain split-K GEMM, 3-stage swizzled pipeline ----------------
template <bool CONV>
__global__ void __launch_bounds__(256, 2)
mma_gemm(const float* __restrict__ Afp,
         const __nv_bfloat16* __restrict__ Ahp, const __nv_bfloat16* __restrict__ Alp,
         const __nv_bfloat16* __restrict__ Bhp, const __nv_bfloat16* __restrict__ Blp,
         float* __restrict__ part, int n, int Kc) {
    extern __shared__ char dyn[];
    uint32_t base = (smem_u32(dyn) + 127) & ~127u;

    const int tid = threadIdx.x, lane = tid & 31, wid = tid >> 5;
    const int warp_m = wid & 3, warp_n = wid >> 2;
    const int rowTile = blockIdx.x * BM;
    const int kbase = blockIdx.y * Kc;
    const int nc = Kc / BK;

    const uint32_t oAh = 0, oAl = TILE_B, oBh = 2 * TILE_B, oBl = 3 * TILE_B;

    const int i0 = tid * 2,       r0 = i0 >> 2, g0 = i0 & 3;
    const int i1 = tid * 2 + 1,   r1 = i1 >> 2, g1 = i1 & 3;
    const uint32_t so0 = swz(r0, g0), so1 = swz(r1, g1);

    const int a_row = tid >> 1;
    const int a_g   = (tid & 1) * 2;
    const uint32_t aso0 = swz(a_row, a_g), aso1 = swz(a_row, a_g + 1);
    float4 av[4];

    auto issue_stage = [&](int c) {
        uint32_t sb = base + (uint32_t)(c % NSTAGE) * STAGE_B;
        int kk = kbase + c * BK;
        cpasync16(sb + oBh + so0, Bhp + (size_t)r0 * n + kk + g0 * 8);
        cpasync16(sb + oBh + so1, Bhp + (size_t)r1 * n + kk + g1 * 8);
        cpasync16(sb + oBl + so0, Blp + (size_t)r0 * n + kk + g0 * 8);
        cpasync16(sb + oBl + so1, Blp + (size_t)r1 * n + kk + g1 * 8);
        if (!CONV) {
            cpasync16(sb + oAh + so0, Ahp + (size_t)(rowTile + r0) * n + kk + g0 * 8);
            cpasync16(sb + oAh + so1, Ahp + (size_t)(rowTile + r1) * n + kk + g1 * 8);
            cpasync16(sb + oAl + so0, Alp + (size_t)(rowTile + r0) * n + kk + g0 * 8);
            cpasync16(sb + oAl + so1, Alp + (size_t)(rowTile + r1) * n + kk + g1 * 8);
        }
        asm volatile("cp.async.commit_group;");
    };
    auto ldg_A = [&](int c) {
        if (CONV) {
            const float4* p = reinterpret_cast<const float4*>(
                Afp + (size_t)(rowTile + a_row) * n + kbase + c * BK + (tid & 1) * 16);
            #pragma unroll
            for (int q = 0; q < 4; q++) av[q] = p[q];
        }
    };
    auto sts_A = [&](int c) {
        if (CONV) {
            uint32_t sb = base + (uint32_t)(c % NSTAGE) * STAGE_B;
            uint32_t h[8], l[8];
            #pragma unroll
            for (int q = 0; q < 4; q++) {
                const float4 v = av[q];
                float hx = __bfloat162float(__float2bfloat16(v.x));
                float hy = __bfloat162float(__float2bfloat16(v.y));
                float hz = __bfloat162float(__float2bfloat16(v.z));
                float hw = __bfloat162float(__float2bfloat16(v.w));
                h[q * 2]     = pack_bf16x2(v.x, v.y);
                h[q * 2 + 1] = pack_bf16x2(v.z, v.w);
                l[q * 2]     = pack_bf16x2(v.x - hx, v.y - hy);
                l[q * 2 + 1] = pack_bf16x2(v.z - hz, v.w - hw);
            }
            asm volatile("st.shared.v4.b32 [%0], {%1,%2,%3,%4};"
                         :: "r"(sb + oAh + aso0), "r"(h[0]), "r"(h[1]), "r"(h[2]), "r"(h[3]));
            asm volatile("st.shared.v4.b32 [%0], {%1,%2,%3,%4};"
                         :: "r"(sb + oAh + aso1), "r"(h[4]), "r"(h[5]), "r"(h[6]), "r"(h[7]));
            asm volatile("st.shared.v4.b32 [%0], {%1,%2,%3,%4};"
                         :: "r"(sb + oAl + aso0), "r"(l[0]), "r"(l[1]), "r"(l[2]), "r"(l[3]));
            asm volatile("st.shared.v4.b32 [%0], {%1,%2,%3,%4};"
                         :: "r"(sb + oAl + aso1), "r"(l[4]), "r"(l[5]), "r"(l[6]), "r"(l[7]));
        }
    };

    float acc[2][8][4];
    #pragma unroll
    for (int i = 0; i < 2; i++)
        #pragma unroll
        for (int j = 0; j < 8; j++)
            #pragma unroll
            for (int q = 0; q < 4; q++) acc[i][j][q] = 0.f;

    const int lr = lane & 7, lsel = lane >> 3;

    issue_stage(0);
    if (CONV) { ldg_A(0); sts_A(0); }
    if (nc > 1) {
        issue_stage(1);
        if (CONV) { ldg_A(1); sts_A(1); }
    }

    for (int c = 0; c < nc; c++) {
        uint32_t sb = base + (uint32_t)(c % NSTAGE) * STAGE_B;
        if (c + 1 < nc) asm volatile("cp.async.wait_group 1;" ::: "memory");
        else            asm volatile("cp.async.wait_group 0;" ::: "memory");
        __syncthreads();

        bool pf = (c + 2 < nc);
        if (pf) { issue_stage(c + 2); ldg_A(c + 2); }

        #pragma unroll
        for (int ks = 0; ks < 2; ks++) {
            uint32_t Ahf[2][4], Alf[2][4];
            #pragma unroll
            for (int mf = 0; mf < 2; mf++) {
                uint32_t row = warp_m * 32 + mf * 16 + lr + (lsel & 1) * 8;
                uint32_t gr  = ks * 2 + (lsel >> 1);
                uint32_t off = swz(row, gr);
                ldsm4(Ahf[mf], sb + oAh + off);
                ldsm4(Alf[mf], sb + oAl + off);
            }
            #pragma unroll
            for (int p = 0; p < 4; p++) {
                uint32_t Bhf[4], Blf[4];
                uint32_t row = warp_n * 64 + p * 16 + lr + (lsel >> 1) * 8;
                uint32_t gr  = ks * 2 + (lsel & 1);
                uint32_t off = swz(row, gr);
                ldsm4(Bhf, sb + oBh + off);
                ldsm4(Blf, sb + oBl + off);
                #pragma unroll
                for (int mf = 0; mf < 2; mf++)
                    #pragma unroll
                    for (int s = 0; s < 2; s++) {
                        int nf = p * 2 + s;
                        mma_bf16(acc[mf][nf], Ahf[mf], Bhf[s * 2], Bhf[s * 2 + 1]);
                        mma_bf16(acc[mf][nf], Ahf[mf], Blf[s * 2], Blf[s * 2 + 1]);
                        mma_bf16(acc[mf][nf], Alf[mf], Bhf[s * 2], Bhf[s * 2 + 1]);
                    }
            }
        }
        if (pf) sts_A(c + 2);
    }

    float* Zp = part + (size_t)blockIdx.y * n * D;
    const int g = lane >> 2, cq = (lane & 3) * 2;
    #pragma unroll
    for (int mf = 0; mf < 2; mf++) {
        int row = rowTile + warp_m * 32 + mf * 16 + g;
        #pragma unroll
        for (int nf = 0; nf < 8; nf++) {
            int col = warp_n * 64 + nf * 8 + cq;
            *reinterpret_cast<float2*>(&Zp[(size_t)row * D + col]) =
                make_float2(acc[mf][nf][0], acc[mf][nf][1]);
            *reinterpret_cast<float2*>(&Zp[(size_t)(row + 8) * D + col]) =
                make_float2(acc[mf][nf][2], acc[mf][nf][3]);
        }
    }
}

// ---------------- deterministic partial reduction + relu (float4) ----------------
__global__ void reduce_relu_kernel(const float* __restrict__ Zpart, float* __restrict__ Z,
                                   int total4, int SK) {
    int i = blockIdx.x * blockDim.x + threadIdx.x;
    if (i >= total4) return;
    float4 s = make_float4(0.f, 0.f, 0.f, 0.f);
    for (int p = 0; p < SK; p++) {
        float4 v = reinterpret_cast<const float4*>(Zpart)[(size_t)p * total4 + i];
        s.x += v.x; s.y += v.y; s.z += v.z; s.w += v.w;
    }
    s.x = fmaxf(s.x, 0.f); s.y = fmaxf(s.y, 0.f);
    s.z = fmaxf(s.z, 0.f); s.w = fmaxf(s.w, 0.f);
    reinterpret_cast<float4*>(Z)[i] = s;
}

// ---------------- fused: partial reduction + relu + next-level score/key + inv reset ----------------
__global__ void reduce_relu_score_kernel(const float* __restrict__ Zpart, float* __restrict__ Z,
                                         int n, int SK, const float* __restrict__ w,
                                         float* __restrict__ score,
                                         unsigned long long* __restrict__ key,
                                         int* __restrict__ inv) {
    int r = blockIdx.x, t = threadIdx.x;
    float s = 0.f;
    for (int p = 0; p < SK; p++) s += Zpart[((size_t)p * n + r) * D + t];
    s = fmaxf(s, 0.f);
    Z[(size_t)r * D + t] = s;
    float wv = w[t];
    float d = s * wv, ww = wv * wv;
    #pragma unroll
    for (int o = 16; o; o >>= 1) {
        d  += __shfl_xor_sync(0xffffffffu, d, o);
        ww += __shfl_xor_sync(0xffffffffu, ww, o);
    }
    __shared__ float sd[4], sw[4];
    int warp = t >> 5, lane = t & 31;
    if (lane == 0) { sd[warp] = d; sw[warp] = ww; }
    __syncthreads();
    if (t == 0) {
        float dd  = sd[0] + sd[1] + sd[2] + sd[3];
        float www = sw[0] + sw[1] + sw[2] + sw[3];
        float sc = tanhf(dd / sqrtf(www));
        score[r] = sc;
        key[r] = score_to_key(sc, r);
        inv[r] = -1;
    }
}

// ---------------- fused UP entry: xA[r] = res[r] + (inv[r]>=0 ? relu(sum_p part[p][inv[r]]) : 0)
__global__ void up_reduce_combine_kernel(const float* __restrict__ Zpart, int kprev, int SK,
                                         const float* __restrict__ res, const int* __restrict__ inv,
                                         float* __restrict__ dst) {
    int r = blockIdx.x, t = threadIdx.x;
    float v = res[(size_t)r * D + t];
    int i = __ldg(&inv[r]);
    if (i >= 0) {
        float s = 0.f;
        for (int p = 0; p < SK; p++)
            s += Zpart[((size_t)p * kprev + i) * D + t];
        v += fmaxf(s, 0.f);
    }
    dst[(size_t)r * D + t] = v;
}

// ---------------- host orchestration (R9 S values: 256 CTAs per GEMM) ----------------
static inline int pick_sk(int n) {
    if (n >= 8192) return 4;
    if (n >= 4096) return 8;
    if (n >= 2048) return 16;
    return 32;
}

extern "C" void kernel_launch(void* const* d_in, const int* in_sizes, int n_in,
                              void* d_out, int out_size) {
    const float* feat = (const float*)d_in[0];
    const float* H    = (const float*)d_in[1];
    const float* pw[3] = {(const float*)d_in[2], (const float*)d_in[3], (const float*)d_in[4]};
    const float* Wd[3] = {(const float*)d_in[5], (const float*)d_in[7], (const float*)d_in[9]};
    const float* bd[3] = {(const float*)d_in[6], (const float*)d_in[8], (const float*)d_in[10]};
    const float* Wu[3] = {(const float*)d_in[11], (const float*)d_in[13], (const float*)d_in[15]};
    const float* bu[3] = {(const float*)d_in[12], (const float*)d_in[14], (const float*)d_in[16]};
    float* out = (float*)d_out;

    float *score, *xA, *xs1, *xs2, *part;
    unsigned long long* key;
    int *perm0, *perm1, *perm2, *inv0, *inv1, *inv2;
    __nv_bfloat16 *yth, *ytl, *Hg0h, *Hg0l, *Hg1h, *Hg1l, *Hg2h, *Hg2l;
    cudaGetSymbolAddress((void**)&score, g_score);
    cudaGetSymbolAddress((void**)&key,   g_key);
    cudaGetSymbolAddress((void**)&perm0, g_perm0);
    cudaGetSymbolAddress((void**)&perm1, g_perm1);
    cudaGetSymbolAddress((void**)&perm2, g_perm2);
    cudaGetSymbolAddress((void**)&inv0,  g_inv0);
    cudaGetSymbolAddress((void**)&inv1,  g_inv1);
    cudaGetSymbolAddress((void**)&inv2,  g_inv2);
    cudaGetSymbolAddress((void**)&xA,    g_xA);
    cudaGetSymbolAddress((void**)&xs1,   g_xs1);
    cudaGetSymbolAddress((void**)&xs2,   g_xs2);
    cudaGetSymbolAddress((void**)&part,  g_part);
    cudaGetSymbolAddress((void**)&yth,   g_yth);
    cudaGetSymbolAddress((void**)&ytl,   g_ytl);
    cudaGetSymbolAddress((void**)&Hg0h,  g_Hg0h);
    cudaGetSymbolAddress((void**)&Hg0l,  g_Hg0l);
    cudaGetSymbolAddress((void**)&Hg1h,  g_Hg1h);
    cudaGetSymbolAddress((void**)&Hg1l,  g_Hg1l);
    cudaGetSymbolAddress((void**)&Hg2h,  g_Hg2h);
    cudaGetSymbolAddress((void**)&Hg2l,  g_Hg2l);

    cudaFuncSetAttribute(gatherH_pipe,    cudaFuncAttributeMaxDynamicSharedMemorySize, 98304);
    cudaFuncSetAttribute(mma_gemm<true>,  cudaFuncAttributeMaxDynamicSharedMemorySize, GEMM_DYN);
    cudaFuncSetAttribute(mma_gemm<false>, cudaFuncAttributeMaxDynamicSharedMemorySize, GEMM_DYN);

    int S;

    // ---------------- DOWN level 0 : n=8192 -> k=4096 ----------------
    score_key_kernel<<<N_NODES / 4, 128>>>(feat, pw[0], score, key, inv0, N_NODES);
    run_sort(key, N_NODES);
    gather_xw_kernel<<<K0 / 16, 128>>>(feat, key, score, Wd[0], bd[0], perm0, inv0, yth, ytl, K0);
    gatherH_pipe<<<K0 / GH_ROWS, GH_THR, (2 * N_NODES + K0) * 4>>>(H, perm0, Hg0h, Hg0l, K0, N_NODES);
    S = pick_sk(K0);
    mma_gemm<false><<<dim3(K0 / BM, S), 256, GEMM_DYN>>>(nullptr, Hg0h, Hg0l, yth, ytl, part, K0, K0 / S);
    reduce_relu_score_kernel<<<K0, 128>>>(part, xs1, K0, S, pw[1], score, key, inv1);

    // ---------------- DOWN level 1 : n=4096 -> k=2048 ----------------
    run_sort(key, K0);
    gather_xw_kernel<<<K1 / 16, 128>>>(xs1, key, score, Wd[1], bd[1], perm1, inv1, yth, ytl, K1);
    gatherH_pipe<<<K1 / GH_ROWS, GH_THR, (2 * K0 + K1) * 4>>>(H, perm1, Hg1h, Hg1l, K1, K0);  // cols < 4096 (bug preserved)
    S = pick_sk(K1);
    mma_gemm<false><<<dim3(K1 / BM, S), 256, GEMM_DYN>>>(nullptr, Hg1h, Hg1l, yth, ytl, part, K1, K1 / S);
    reduce_relu_score_kernel<<<K1, 128>>>(part, xs2, K1, S, pw[2], score, key, inv2);

    // ---------------- DOWN level 2 : n=2048 -> k=1024 ----------------
    run_sort(key, K1);
    gather_xw_kernel<<<K2 / 16, 128>>>(xs2, key, score, Wd[2], bd[2], perm2, inv2, yth, ytl, K2);
    gatherH_pipe<<<K2 / GH_ROWS, GH_THR, (2 * K1 + K2) * 4>>>(H, perm2, Hg2h, Hg2l, K2, K1);  // cols < 2048
    S = pick_sk(K2);
    mma_gemm<false><<<dim3(K2 / BM, S), 256, GEMM_DYN>>>(nullptr, Hg2h, Hg2l, yth, ytl, part, K2, K2 / S);
    int S_d2 = S;

    // ---------------- UP i=0 (j=2): res=xs2(2048), graph=Hg1, inv2 ----------------
    up_reduce_combine_kernel<<<K1, 128>>>(part, K2, S_d2, xs2, inv2, xA);
    xw_trans_kernel<<<K1 / 16, 128>>>(xA, Wu[0], bu[0], yth, ytl, K1);
    S = pick_sk(K1);
    mma_gemm<false><<<dim3(K1 / BM, S), 256, GEMM_DYN>>>(nullptr, Hg1h, Hg1l, yth, ytl, part, K1, K1 / S);
    int S_u0 = S;

    // ---------------- UP i=1 (j=1): res=xs1(4096), graph=Hg0, inv1 ----------------
    up_reduce_combine_kernel<<<K0, 128>>>(part, K1, S_u0, xs1, inv1, xA);
    xw_trans_kernel<<<K0 / 16, 128>>>(xA, Wu[1], bu[1], yth, ytl, K0);
    S = pick_sk(K0);
    mma_gemm<false><<<dim3(K0 / BM, S), 256, GEMM_DYN>>>(nullptr, Hg0h, Hg0l, yth, ytl, part, K0, K0 / S);
    int S_u1 = S;

    // ---------------- UP i=2 (j=0): res=feat(8192), graph=H (fp32, convert), inv0 ----------------
    up_reduce_combine_kernel<<<N_NODES, 128>>>(part, K0, S_u1, feat, inv0, xA);
    xw_trans_kernel<<<N_NODES / 16, 128>>>(xA, Wu[2], bu[2], yth, ytl, N_NODES);
    S = pick_sk(N_NODES);
    mma_gemm<true><<<dim3(N_NODES / BM, S), 256, GEMM_DYN>>>(H, nullptr, nullptr, yth, ytl, part, N_NODES, N_NODES / S);
    reduce_relu_kernel<<<(N_NODES * D / 4 + 255) / 256, 256>>>(part, out, N_NODES * D / 4, S);
}

// round 16
// speedup vs baseline: 1.0346x; 1.0346x over previous
#include <cuda_runtime.h>
#include <cuda_bf16.h>
#include <stdint.h>

#define N_NODES 8192
#define D 128
#define K0 4096
#define K1 2048
#define K2 1024

// GEMM tile config: 128x128 CTA tile, BK=32, 3-stage cp.async pipeline,
// XOR-swizzled smem (64B rows, granule' = g ^ ((row>>1)&3)) -> no padding.
#define BM 128
#define BK 32
#define TILE_B (128 * 64)                // 8192 bytes per tile plane
#define STAGE_B (4 * TILE_B)             // Ah, Al, Bh, Bl = 32 KB
#define NSTAGE 3
#define GEMM_DYN (NSTAGE * STAGE_B + 256)

#define SORT_TILE 2048
#define GH_ROWS 8                        // rows per gatherH block (double-buffered)
#define GH_THR 1024

// ---------------- scratch (static __device__ arrays; no allocs) ----------------
__device__ __align__(256) float               g_score[N_NODES];
__device__ __align__(256) unsigned long long  g_key[N_NODES];
__device__ __align__(256) int                 g_perm0[K0];
__device__ __align__(256) int                 g_perm1[K1];
__device__ __align__(256) int                 g_perm2[K2];
__device__ __align__(256) int                 g_inv0[N_NODES];
__device__ __align__(256) int                 g_inv1[K0];
__device__ __align__(256) int                 g_inv2[K1];
__device__ __align__(256) float               g_xA[N_NODES * D];
__device__ __align__(256) float               g_xB[N_NODES * D];
__device__ __align__(256) float               g_xs1[K0 * D];
__device__ __align__(256) float               g_xs2[K1 * D];
__device__ __align__(256) __nv_bfloat16       g_Hg0h[(size_t)K0 * K0];
__device__ __align__(256) __nv_bfloat16       g_Hg0l[(size_t)K0 * K0];
__device__ __align__(256) __nv_bfloat16       g_Hg1h[(size_t)K1 * K1];
__device__ __align__(256) __nv_bfloat16       g_Hg1l[(size_t)K1 * K1];
__device__ __align__(256) __nv_bfloat16       g_Hg2h[(size_t)K2 * K2];
__device__ __align__(256) __nv_bfloat16       g_Hg2l[(size_t)K2 * K2];
__device__ __align__(256) float               g_part[4 * 1024 * 1024];
__device__ __align__(256) __nv_bfloat16       g_yth[D * N_NODES];
__device__ __align__(256) __nv_bfloat16       g_ytl[D * N_NODES];

// ---------------- PTX helpers ----------------
__device__ __forceinline__ uint32_t smem_u32(const void* p) {
    uint32_t a;
    asm("{ .reg .u64 t; cvta.to.shared.u64 t, %1; cvt.u32.u64 %0, t; }" : "=r"(a) : "l"(p));
    return a;
}
__device__ __forceinline__ void cpasync16(uint32_t dst, const void* src) {
    asm volatile("cp.async.cg.shared.global [%0], [%1], 16;" :: "r"(dst), "l"(src));
}
__device__ __forceinline__ void ldsm4(uint32_t* r, uint32_t a) {
    asm volatile("ldmatrix.sync.aligned.m8n8.x4.shared.b16 {%0,%1,%2,%3}, [%4];"
                 : "=r"(r[0]), "=r"(r[1]), "=r"(r[2]), "=r"(r[3]) : "r"(a));
}
__device__ __forceinline__ void mma_bf16(float* c, const uint32_t* a, uint32_t b0, uint32_t b1) {
    asm volatile("mma.sync.aligned.m16n8k16.row.col.f32.bf16.bf16.f32 "
                 "{%0,%1,%2,%3}, {%4,%5,%6,%7}, {%8,%9}, {%0,%1,%2,%3};"
                 : "+f"(c[0]), "+f"(c[1]), "+f"(c[2]), "+f"(c[3])
                 : "r"(a[0]), "r"(a[1]), "r"(a[2]), "r"(a[3]), "r"(b0), "r"(b1));
}
__device__ __forceinline__ uint32_t pack_bf16x2(float a, float b) {
    __nv_bfloat162 t = __floats2bfloat162_rn(a, b);
    return *reinterpret_cast<uint32_t*>(&t);
}
__device__ __forceinline__ unsigned long long score_to_key(float s, int row) {
    unsigned int b = __float_as_uint(s);
    b ^= (b & 0x80000000u) ? 0xFFFFFFFFu : 0x80000000u;
    unsigned int desc = ~b;
    return (((unsigned long long)desc) << 32) | (unsigned int)row;
}
__device__ __forceinline__ uint32_t swz(uint32_t row, uint32_t gran) {
    return row * 64u + ((gran ^ ((row >> 1) & 3u)) * 16u);
}

// ---------------- score + sort key (also resets inv) ----------------
__global__ void score_key_kernel(const float* __restrict__ x, const float* __restrict__ w,
                                 float* __restrict__ score, unsigned long long* __restrict__ key,
                                 int* __restrict__ inv, int n) {
    int warp = threadIdx.x >> 5, lane = threadIdx.x & 31;
    int row = blockIdx.x * (blockDim.x >> 5) + warp;
    if (row >= n) return;
    float4 xv = reinterpret_cast<const float4*>(x + (size_t)row * D)[lane];
    float4 wv = reinterpret_cast<const float4*>(w)[lane];
    float d  = xv.x * wv.x + xv.y * wv.y + xv.z * wv.z + xv.w * wv.w;
    float ww = wv.x * wv.x + wv.y * wv.y + wv.z * wv.z + wv.w * wv.w;
    #pragma unroll
    for (int o = 16; o; o >>= 1) {
        d  += __shfl_xor_sync(0xffffffffu, d, o);
        ww += __shfl_xor_sync(0xffffffffu, ww, o);
    }
    if (lane == 0) {
        float s = tanhf(d / sqrtf(ww));
        score[row] = s;
        key[row] = score_to_key(s, row);
        inv[row] = -1;
    }
}

// ---------------- tiled bitonic sort (R9 proven structure) ----------------
__global__ void sort_local(unsigned long long* __restrict__ key) {
    __shared__ unsigned long long s[SORT_TILE];
    int tid = threadIdx.x;
    int base = blockIdx.x * SORT_TILE;
    s[tid] = key[base + tid];
    s[tid + 1024] = key[base + tid + 1024];
    __syncthreads();
    for (int ksz = 2; ksz <= SORT_TILE; ksz <<= 1) {
        for (int j = ksz >> 1; j > 0; j >>= 1) {
            int i = ((tid & ~(j - 1)) << 1) | (tid & (j - 1));
            int x = i | j;
            bool up = (((base + i) & ksz) == 0);
            unsigned long long a = s[i], b = s[x];
            if ((a > b) == up) { s[i] = b; s[x] = a; }
            if (j > 32 || j == 1) __syncthreads(); else __syncwarp();
        }
    }
    key[base + tid] = s[tid];
    key[base + tid + 1024] = s[tid + 1024];
}

__global__ void lmerge(unsigned long long* __restrict__ key, int ksz) {
    __shared__ unsigned long long s[SORT_TILE];
    int tid = threadIdx.x;
    int base = blockIdx.x * SORT_TILE;
    s[tid] = key[base + tid];
    s[tid + 1024] = key[base + tid + 1024];
    __syncthreads();
    for (int j = SORT_TILE >> 1; j > 0; j >>= 1) {
        int i = ((tid & ~(j - 1)) << 1) | (tid & (j - 1));
        int x = i | j;
        bool up = (((base + i) & ksz) == 0);
        unsigned long long a = s[i], b = s[x];
        if ((a > b) == up) { s[i] = b; s[x] = a; }
        if (j > 32 || j == 1) __syncthreads(); else __syncwarp();
    }
    key[base + tid] = s[tid];
    key[base + tid + 1024] = s[tid + 1024];
}

__global__ void gmerge(unsigned long long* __restrict__ key, int ksz, int j) {
    int p = blockIdx.x * blockDim.x + threadIdx.x;
    int i = ((p & ~(j - 1)) << 1) | (p & (j - 1));
    int x = i | j;
    bool up = ((i & ksz) == 0);
    unsigned long long a = key[i], b = key[x];
    if ((a > b) == up) { key[i] = b; key[x] = a; }
}

__global__ void gmerge2_8192(unsigned long long* __restrict__ key) {
    int q = blockIdx.x * blockDim.x + threadIdx.x;  // 0..2047
    unsigned long long a0 = key[q], a1 = key[q + 2048], a2 = key[q + 4096], a3 = key[q + 6144];
    unsigned long long t;
    if (a0 > a2) { t = a0; a0 = a2; a2 = t; }
    if (a1 > a3) { t = a1; a1 = a3; a3 = t; }
    if (a0 > a1) { t = a0; a0 = a1; a1 = t; }
    if (a2 > a3) { t = a2; a2 = a3; a3 = t; }
    key[q] = a0; key[q + 2048] = a1; key[q + 4096] = a2; key[q + 6144] = a3;
}

static void run_sort(unsigned long long* key, int n) {
    sort_local<<<n / SORT_TILE, 1024>>>(key);
    if (n >= 4096) {
        gmerge<<<n / 512, 256>>>(key, 4096, 2048);
        lmerge<<<n / SORT_TILE, 1024>>>(key, 4096);
    }
    if (n >= 8192) {
        gmerge2_8192<<<8, 256>>>(key);
        lmerge<<<n / SORT_TILE, 1024>>>(key, 8192);
    }
}

// ---------------- gather rows + gate by score, emit perm + inverse ----------------
__global__ void gather_gate_kernel(const float* __restrict__ xin,
                                   const unsigned long long* __restrict__ key,
                                   const float* __restrict__ score,
                                   float* __restrict__ xout, int* __restrict__ perm,
                                   int* __restrict__ inv, int k) {
    int i = blockIdx.x;
    int p = (int)(key[i] & 0xffffffffu);
    if (threadIdx.x == 0) { perm[i] = p; inv[p] = i; }
    float s = score[p];
    xout[(size_t)i * D + threadIdx.x] = xin[(size_t)p * D + threadIdx.x] * s;
}

// ---------------- H[perm][:,perm] -> bf16 hi/lo planes, cp.async double-buffered ----------------
__global__ void gatherH_pipe(const float* __restrict__ H, const int* __restrict__ perm,
                             __nv_bfloat16* __restrict__ Hh, __nv_bfloat16* __restrict__ Hl,
                             int k, int rowW) {
    extern __shared__ float sm[];
    float* buf0 = sm;
    float* buf1 = sm + rowW;
    int* ps = (int*)(sm + 2 * rowW);
    const int tid = threadIdx.x;            // GH_THR
    const int i0 = blockIdx.x * GH_ROWS;
    const int nch = rowW / 4;                // 16B chunks per row

    for (int j = tid; j < k; j += GH_THR) ps[j] = __ldg(&perm[j]);

    // prologue: stage row 0
    {
        int pi = __ldg(&perm[i0]);
        const char* src = (const char*)(H + (size_t)pi * N_NODES);
        uint32_t dst = smem_u32(buf0);
        for (int c = tid; c < nch; c += GH_THR) cpasync16(dst + c * 16u, src + (size_t)c * 16);
        asm volatile("cp.async.commit_group;");
    }

    for (int r = 0; r < GH_ROWS; r++) {
        asm volatile("cp.async.wait_group 0;" ::: "memory");
        __syncthreads();    // row r visible; all threads done gathering row r-1 (frees alt buffer)
        if (r + 1 < GH_ROWS) {
            int pi = __ldg(&perm[i0 + r + 1]);
            const char* src = (const char*)(H + (size_t)pi * N_NODES);
            uint32_t dst = smem_u32(((r + 1) & 1) ? buf1 : buf0);
            for (int c = tid; c < nch; c += GH_THR) cpasync16(dst + c * 16u, src + (size_t)c * 16);
            asm volatile("cp.async.commit_group;");
        }
        const float* rowf = (r & 1) ? buf1 : buf0;
        int i = i0 + r;
        __nv_bfloat16* dh = Hh + (size_t)i * k;
        __nv_bfloat16* dl = Hl + (size_t)i * k;
        for (int j0 = tid * 8; j0 < k; j0 += GH_THR * 8) {
            uint32_t hv[4], lv[4];
            #pragma unroll
            for (int q = 0; q < 4; q++) {
                float v0 = rowf[ps[j0 + 2 * q]];
                float v1 = rowf[ps[j0 + 2 * q + 1]];
                float h0 = __bfloat162float(__float2bfloat16(v0));
                float h1 = __bfloat162float(__float2bfloat16(v1));
                hv[q] = pack_bf16x2(v0, v1);
                lv[q] = pack_bf16x2(v0 - h0, v1 - h1);
            }
            *reinterpret_cast<uint4*>(dh + j0) = make_uint4(hv[0], hv[1], hv[2], hv[3]);
            *reinterpret_cast<uint4*>(dl + j0) = make_uint4(lv[0], lv[1], lv[2], lv[3]);
        }
    }
}

// ---------------- Yt = (X @ W + b)^T as bf16 hi/lo planes [128 x n] ----------------
__global__ void xw_trans_kernel(const float* __restrict__ X, const float* __restrict__ W,
                                const float* __restrict__ b,
                                __nv_bfloat16* __restrict__ Yh, __nv_bfloat16* __restrict__ Yl,
                                int n) {
    __shared__ float xs[16][D];
    int r0 = blockIdx.x * 16;
    int tid = threadIdx.x;
    #pragma unroll
    for (int r = 0; r < 16; r++) xs[r][tid] = X[(size_t)(r0 + r) * D + tid];
    __syncthreads();
    float bv = b[tid];
    float acc[16];
    #pragma unroll
    for (int r = 0; r < 16; r++) acc[r] = bv;
    #pragma unroll 4
    for (int kk = 0; kk < D; kk++) {
        float wv = W[kk * D + tid];
        #pragma unroll
        for (int r = 0; r < 16; r++) acc[r] += xs[r][kk] * wv;
    }
    #pragma unroll
    for (int r = 0; r < 16; r++) {
        float v = acc[r];
        __nv_bfloat16 h = __float2bfloat16(v);
        Yh[(size_t)tid * n + r0 + r] = h;
        Yl[(size_t)tid * n + r0 + r] = __float2bfloat16(v - __bfloat162float(h));
    }
}

// ---------------- mma.sync bf16 3-chain split-K GEMM, 3-stage swizzled pipeline ----------------
template <bool CONV>
__global__ void __launch_bounds__(256, 2)
mma_gemm(const float* __restrict__ Afp,
         const __nv_bfloat16* __restrict__ Ahp, const __nv_bfloat16* __restrict__ Alp,
         const __nv_bfloat16* __restrict__ Bhp, const __nv_bfloat16* __restrict__ Blp,
         float* __restrict__ part, int n, int Kc) {
    extern __shared__ char dyn[];
    uint32_t base = (smem_u32(dyn) + 127) & ~127u;

    const int tid = threadIdx.x, lane = tid & 31, wid = tid >> 5;
    const int warp_m = wid & 3, warp_n = wid >> 2;
    const int rowTile = blockIdx.x * BM;
    const int kbase = blockIdx.y * Kc;
    const int nc = Kc / BK;

    const uint32_t oAh = 0, oAl = TILE_B, oBh = 2 * TILE_B, oBl = 3 * TILE_B;

    const int i0 = tid * 2,       r0 = i0 >> 2, g0 = i0 & 3;
    const int i1 = tid * 2 + 1,   r1 = i1 >> 2, g1 = i1 & 3;
    const uint32_t so0 = swz(r0, g0), so1 = swz(r1, g1);

    const int a_row = tid >> 1;
    const int a_g   = (tid & 1) * 2;
    const uint32_t aso0 = swz(a_row, a_g), aso1 = swz(a_row, a_g + 1);
    float4 av[4];

    auto issue_stage = [&](int c) {
        uint32_t sb = base + (uint32_t)(c % NSTAGE) * STAGE_B;
        int kk = kbase + c * BK;
        cpasync16(sb + oBh + so0, Bhp + (size_t)r0 * n + kk + g0 * 8);
        cpasync16(sb + oBh + so1, Bhp + (size_t)r1 * n + kk + g1 * 8);
        cpasync16(sb + oBl + so0, Blp + (size_t)r0 * n + kk + g0 * 8);
        cpasync16(sb + oBl + so1, Blp + (size_t)r1 * n + kk + g1 * 8);
        if (!CONV) {
            cpasync16(sb + oAh + so0, Ahp + (size_t)(rowTile + r0) * n + kk + g0 * 8);
            cpasync16(sb + oAh + so1, Ahp + (size_t)(rowTile + r1) * n + kk + g1 * 8);
            cpasync16(sb + oAl + so0, Alp + (size_t)(rowTile + r0) * n + kk + g0 * 8);
            cpasync16(sb + oAl + so1, Alp + (size_t)(rowTile + r1) * n + kk + g1 * 8);
        }
        asm volatile("cp.async.commit_group;");
    };
    auto ldg_A = [&](int c) {
        if (CONV) {
            const float4* p = reinterpret_cast<const float4*>(
                Afp + (size_t)(rowTile + a_row) * n + kbase + c * BK + (tid & 1) * 16);
            #pragma unroll
            for (int q = 0; q < 4; q++) av[q] = p[q];
        }
    };
    auto sts_A = [&](int c) {
        if (CONV) {
            uint32_t sb = base + (uint32_t)(c % NSTAGE) * STAGE_B;
            uint32_t h[8], l[8];
            #pragma unroll
            for (int q = 0; q < 4; q++) {
                const float4 v = av[q];
                float hx = __bfloat162float(__float2bfloat16(v.x));
                float hy = __bfloat162float(__float2bfloat16(v.y));
                float hz = __bfloat162float(__float2bfloat16(v.z));
                float hw = __bfloat162float(__float2bfloat16(v.w));
                h[q * 2]     = pack_bf16x2(v.x, v.y);
                h[q * 2 + 1] = pack_bf16x2(v.z, v.w);
                l[q * 2]     = pack_bf16x2(v.x - hx, v.y - hy);
                l[q * 2 + 1] = pack_bf16x2(v.z - hz, v.w - hw);
            }
            asm volatile("st.shared.v4.b32 [%0], {%1,%2,%3,%4};"
                         :: "r"(sb + oAh + aso0), "r"(h[0]), "r"(h[1]), "r"(h[2]), "r"(h[3]));
            asm volatile("st.shared.v4.b32 [%0], {%1,%2,%3,%4};"
                         :: "r"(sb + oAh + aso1), "r"(h[4]), "r"(h[5]), "r"(h[6]), "r"(h[7]));
            asm volatile("st.shared.v4.b32 [%0], {%1,%2,%3,%4};"
                         :: "r"(sb + oAl + aso0), "r"(l[0]), "r"(l[1]), "r"(l[2]), "r"(l[3]));
            asm volatile("st.shared.v4.b32 [%0], {%1,%2,%3,%4};"
                         :: "r"(sb + oAl + aso1), "r"(l[4]), "r"(l[5]), "r"(l[6]), "r"(l[7]));
        }
    };

    float acc[2][8][4];
    #pragma unroll
    for (int i = 0; i < 2; i++)
        #pragma unroll
        for (int j = 0; j < 8; j++)
            #pragma unroll
            for (int q = 0; q < 4; q++) acc[i][j][q] = 0.f;

    const int lr = lane & 7, lsel = lane >> 3;

    issue_stage(0);
    if (CONV) { ldg_A(0); sts_A(0); }
    if (nc > 1) {
        issue_stage(1);
        if (CONV) { ldg_A(1); sts_A(1); }
    }

    for (int c = 0; c < nc; c++) {
        uint32_t sb = base + (uint32_t)(c % NSTAGE) * STAGE_B;
        if (c + 1 < nc) asm volatile("cp.async.wait_group 1;" ::: "memory");
        else            asm volatile("cp.async.wait_group 0;" ::: "memory");
        __syncthreads();

        bool pf = (c + 2 < nc);
        if (pf) { issue_stage(c + 2); ldg_A(c + 2); }

        #pragma unroll
        for (int ks = 0; ks < 2; ks++) {
            uint32_t Ahf[2][4], Alf[2][4];
            #pragma unroll
            for (int mf = 0; mf < 2; mf++) {
                uint32_t row = warp_m * 32 + mf * 16 + lr + (lsel & 1) * 8;
                uint32_t gr  = ks * 2 + (lsel >> 1);
                uint32_t off = swz(row, gr);
                ldsm4(Ahf[mf], sb + oAh + off);
                ldsm4(Alf[mf], sb + oAl + off);
            }
            #pragma unroll
            for (int p = 0; p < 4; p++) {
                uint32_t Bhf[4], Blf[4];
                uint32_t row = warp_n * 64 + p * 16 + lr + (lsel >> 1) * 8;
                uint32_t gr  = ks * 2 + (lsel & 1);
                uint32_t off = swz(row, gr);
                ldsm4(Bhf, sb + oBh + off);
                ldsm4(Blf, sb + oBl + off);
                #pragma unroll
                for (int mf = 0; mf < 2; mf++)
                    #pragma unroll
                    for (int s = 0; s < 2; s++) {
                        int nf = p * 2 + s;
                        mma_bf16(acc[mf][nf], Ahf[mf], Bhf[s * 2], Bhf[s * 2 + 1]);
                        mma_bf16(acc[mf][nf], Ahf[mf], Blf[s * 2], Blf[s * 2 + 1]);
                        mma_bf16(acc[mf][nf], Alf[mf], Bhf[s * 2], Bhf[s * 2 + 1]);
                    }
            }
        }
        if (pf) sts_A(c + 2);
    }

    float* Zp = part + (size_t)blockIdx.y * n * D;
    const int g = lane >> 2, cq = (lane & 3) * 2;
    #pragma unroll
    for (int mf = 0; mf < 2; mf++) {
        int row = rowTile + warp_m * 32 + mf * 16 + g;
        #pragma unroll
        for (int nf = 0; nf < 8; nf++) {
            int col = warp_n * 64 + nf * 8 + cq;
            *reinterpret_cast<float2*>(&Zp[(size_t)row * D + col]) =
                make_float2(acc[mf][nf][0], acc[mf][nf][1]);
            *reinterpret_cast<float2*>(&Zp[(size_t)(row + 8) * D + col]) =
                make_float2(acc[mf][nf][2], acc[mf][nf][3]);
        }
    }
}

// ---------------- deterministic partial reduction + relu (float4) ----------------
__global__ void reduce_relu_kernel(const float* __restrict__ Zpart, float* __restrict__ Z,
                                   int total4, int SK) {
    int i = blockIdx.x * blockDim.x + threadIdx.x;
    if (i >= total4) return;
    float4 s = make_float4(0.f, 0.f, 0.f, 0.f);
    for (int p = 0; p < SK; p++) {
        float4 v = reinterpret_cast<const float4*>(Zpart)[(size_t)p * total4 + i];
        s.x += v.x; s.y += v.y; s.z += v.z; s.w += v.w;
    }
    s.x = fmaxf(s.x, 0.f); s.y = fmaxf(s.y, 0.f);
    s.z = fmaxf(s.z, 0.f); s.w = fmaxf(s.w, 0.f);
    reinterpret_cast<float4*>(Z)[i] = s;
}

// ---------------- fused: partial reduction + relu + next-level score/key + inv reset ----------------
__global__ void reduce_relu_score_kernel(const float* __restrict__ Zpart, float* __restrict__ Z,
                                         int n, int SK, const float* __restrict__ w,
                                         float* __restrict__ score,
                                         unsigned long long* __restrict__ key,
                                         int* __restrict__ inv) {
    int r = blockIdx.x, t = threadIdx.x;
    float s = 0.f;
    for (int p = 0; p < SK; p++) s += Zpart[((size_t)p * n + r) * D + t];
    s = fmaxf(s, 0.f);
    Z[(size_t)r * D + t] = s;
    float wv = w[t];
    float d = s * wv, ww = wv * wv;
    #pragma unroll
    for (int o = 16; o; o >>= 1) {
        d  += __shfl_xor_sync(0xffffffffu, d, o);
        ww += __shfl_xor_sync(0xffffffffu, ww, o);
    }
    __shared__ float sd[4], sw[4];
    int warp = t >> 5, lane = t & 31;
    if (lane == 0) { sd[warp] = d; sw[warp] = ww; }
    __syncthreads();
    if (t == 0) {
        float dd  = sd[0] + sd[1] + sd[2] + sd[3];
        float www = sw[0] + sw[1] + sw[2] + sw[3];
        float sc = tanhf(dd / sqrtf(www));
        score[r] = sc;
        key[r] = score_to_key(sc, r);
        inv[r] = -1;
    }
}

// ---------------- fused UP entry: xA[r] = res[r] + (inv[r]>=0 ? relu(sum_p part[p][inv[r]]) : 0)
__global__ void up_reduce_combine_kernel(const float* __restrict__ Zpart, int kprev, int SK,
                                         const float* __restrict__ res, const int* __restrict__ inv,
                                         float* __restrict__ dst) {
    int r = blockIdx.x, t = threadIdx.x;
    float v = res[(size_t)r * D + t];
    int i = __ldg(&inv[r]);
    if (i >= 0) {
        float s = 0.f;
        for (int p = 0; p < SK; p++)
            s += Zpart[((size_t)p * kprev + i) * D + t];
        v += fmaxf(s, 0.f);
    }
    dst[(size_t)r * D + t] = v;
}

// ---------------- host orchestration (R9 S values: 256 CTAs per GEMM) ----------------
static inline int pick_sk(int n) {
    if (n >= 8192) return 4;
    if (n >= 4096) return 8;
    if (n >= 2048) return 16;
    return 32;
}

extern "C" void kernel_launch(void* const* d_in, const int* in_sizes, int n_in,
                              void* d_out, int out_size) {
    const float* feat = (const float*)d_in[0];
    const float* H    = (const float*)d_in[1];
    const float* pw[3] = {(const float*)d_in[2], (const float*)d_in[3], (const float*)d_in[4]};
    const float* Wd[3] = {(const float*)d_in[5], (const float*)d_in[7], (const float*)d_in[9]};
    const float* bd[3] = {(const float*)d_in[6], (const float*)d_in[8], (const float*)d_in[10]};
    const float* Wu[3] = {(const float*)d_in[11], (const float*)d_in[13], (const float*)d_in[15]};
    const float* bu[3] = {(const float*)d_in[12], (const float*)d_in[14], (const float*)d_in[16]};
    float* out = (float*)d_out;

    float *score, *xA, *xs1, *xs2, *part;
    unsigned long long* key;
    int *perm0, *perm1, *perm2, *inv0, *inv1, *inv2;
    __nv_bfloat16 *yth, *ytl, *Hg0h, *Hg0l, *Hg1h, *Hg1l, *Hg2h, *Hg2l;
    cudaGetSymbolAddress((void**)&score, g_score);
    cudaGetSymbolAddress((void**)&key,   g_key);
    cudaGetSymbolAddress((void**)&perm0, g_perm0);
    cudaGetSymbolAddress((void**)&perm1, g_perm1);
    cudaGetSymbolAddress((void**)&perm2, g_perm2);
    cudaGetSymbolAddress((void**)&inv0,  g_inv0);
    cudaGetSymbolAddress((void**)&inv1,  g_inv1);
    cudaGetSymbolAddress((void**)&inv2,  g_inv2);
    cudaGetSymbolAddress((void**)&xA,    g_xA);
    cudaGetSymbolAddress((void**)&xs1,   g_xs1);
    cudaGetSymbolAddress((void**)&xs2,   g_xs2);
    cudaGetSymbolAddress((void**)&part,  g_part);
    cudaGetSymbolAddress((void**)&yth,   g_yth);
    cudaGetSymbolAddress((void**)&ytl,   g_ytl);
    cudaGetSymbolAddress((void**)&Hg0h,  g_Hg0h);
    cudaGetSymbolAddress((void**)&Hg0l,  g_Hg0l);
    cudaGetSymbolAddress((void**)&Hg1h,  g_Hg1h);
    cudaGetSymbolAddress((void**)&Hg1l,  g_Hg1l);
    cudaGetSymbolAddress((void**)&Hg2h,  g_Hg2h);
    cudaGetSymbolAddress((void**)&Hg2l,  g_Hg2l);

    cudaFuncSetAttribute(gatherH_pipe,    cudaFuncAttributeMaxDynamicSharedMemorySize, 98304);
    cudaFuncSetAttribute(mma_gemm<true>,  cudaFuncAttributeMaxDynamicSharedMemorySize, GEMM_DYN);
    cudaFuncSetAttribute(mma_gemm<false>, cudaFuncAttributeMaxDynamicSharedMemorySize, GEMM_DYN);

    int S;

    // ---------------- DOWN level 0 : n=8192 -> k=4096 ----------------
    score_key_kernel<<<N_NODES / 4, 128>>>(feat, pw[0], score, key, inv0, N_NODES);
    run_sort(key, N_NODES);
    gather_gate_kernel<<<K0, 128>>>(feat, key, score, xA, perm0, inv0, K0);
    gatherH_pipe<<<K0 / GH_ROWS, GH_THR, (2 * N_NODES + K0) * 4>>>(H, perm0, Hg0h, Hg0l, K0, N_NODES);
    xw_trans_kernel<<<K0 / 16, 128>>>(xA, Wd[0], bd[0], yth, ytl, K0);
    S = pick_sk(K0);
    mma_gemm<false><<<dim3(K0 / BM, S), 256, GEMM_DYN>>>(nullptr, Hg0h, Hg0l, yth, ytl, part, K0, K0 / S);
    reduce_relu_score_kernel<<<K0, 128>>>(part, xs1, K0, S, pw[1], score, key, inv1);

    // ---------------- DOWN level 1 : n=4096 -> k=2048 ----------------
    run_sort(key, K0);
    gather_gate_kernel<<<K1, 128>>>(xs1, key, score, xA, perm1, inv1, K1);
    gatherH_pipe<<<K1 / GH_ROWS, GH_THR, (2 * K0 + K1) * 4>>>(H, perm1, Hg1h, Hg1l, K1, K0);  // cols < 4096 (bug preserved)
    xw_trans_kernel<<<K1 / 16, 128>>>(xA, Wd[1], bd[1], yth, ytl, K1);
    S = pick_sk(K1);
    mma_gemm<false><<<dim3(K1 / BM, S), 256, GEMM_DYN>>>(nullptr, Hg1h, Hg1l, yth, ytl, part, K1, K1 / S);
    reduce_relu_score_kernel<<<K1, 128>>>(part, xs2, K1, S, pw[2], score, key, inv2);

    // ---------------- DOWN level 2 : n=2048 -> k=1024 ----------------
    run_sort(key, K1);
    gather_gate_kernel<<<K2, 128>>>(xs2, key, score, xA, perm2, inv2, K2);
    gatherH_pipe<<<K2 / GH_ROWS, GH_THR, (2 * K1 + K2) * 4>>>(H, perm2, Hg2h, Hg2l, K2, K1);  // cols < 2048
    xw_trans_kernel<<<K2 / 16, 128>>>(xA, Wd[2], bd[2], yth, ytl, K2);
    S = pick_sk(K2);
    mma_gemm<false><<<dim3(K2 / BM, S), 256, GEMM_DYN>>>(nullptr, Hg2h, Hg2l, yth, ytl, part, K2, K2 / S);
    int S_d2 = S;

    // ---------------- UP i=0 (j=2): res=xs2(2048), graph=Hg1, inv2 ----------------
    up_reduce_combine_kernel<<<K1, 128>>>(part, K2, S_d2, xs2, inv2, xA);
    xw_trans_kernel<<<K1 / 16, 128>>>(xA, Wu[0], bu[0], yth, ytl, K1);
    S = pick_sk(K1);
    mma_gemm<false><<<dim3(K1 / BM, S), 256, GEMM_DYN>>>(nullptr, Hg1h, Hg1l, yth, ytl, part, K1, K1 / S);
    int S_u0 = S;

    // ---------------- UP i=1 (j=1): res=xs1(4096), graph=Hg0, inv1 ----------------
    up_reduce_combine_kernel<<<K0, 128>>>(part, K1, S_u0, xs1, inv1, xA);
    xw_trans_kernel<<<K0 / 16, 128>>>(xA, Wu[1], bu[1], yth, ytl, K0);
    S = pick_sk(K0);
    mma_gemm<false><<<dim3(K0 / BM, S), 256, GEMM_DYN>>>(nullptr, Hg0h, Hg0l, yth, ytl, part, K0, K0 / S);
    int S_u1 = S;

    // ---------------- UP i=2 (j=0): res=feat(8192), graph=H (fp32, convert), inv0 ----------------
    up_reduce_combine_kernel<<<N_NODES, 128>>>(part, K0, S_u1, feat, inv0, xA);
    xw_trans_kernel<<<N_NODES / 16, 128>>>(xA, Wu[2], bu[2], yth, ytl, N_NODES);
    S = pick_sk(N_NODES);
    mma_gemm<true><<<dim3(N_NODES / BM, S), 256, GEMM_DYN>>>(H, nullptr, nullptr, yth, ytl, part, N_NODES, N_NODES / S);
    reduce_relu_kernel<<<(N_NODES * D / 4 + 255) / 256, 256>>>(part, out, N_NODES * D / 4, S);
}

// round 17
// speedup vs baseline: 1.1381x; 1.1001x over previous
#include <cuda_runtime.h>
#include <cuda_bf16.h>
#include <stdint.h>

#define N_NODES 8192
#define D 128
#define K0 4096
#define K1 2048
#define K2 1024

// GEMM tile config: 128x128 CTA tile, BK=32, 3-stage cp.async pipeline,
// XOR-swizzled smem (64B rows, granule' = g ^ ((row>>1)&3)) -> no padding.
#define BM 128
#define BK 32
#define TILE_B (128 * 64)                // 8192 bytes per tile plane
#define STAGE_B (4 * TILE_B)             // Ah, Al, Bh, Bl = 32 KB
#define NSTAGE 3
#define GEMM_DYN (NSTAGE * STAGE_B + 256)

#define SORT_TILE 2048
#define GH_ROWS 8                        // rows per gatherH block (double-buffered)
#define GH_THR 1024

// ---------------- scratch (static __device__ arrays; no allocs) ----------------
__device__ __align__(256) float               g_score[N_NODES];
__device__ __align__(256) unsigned long long  g_key[N_NODES];
__device__ __align__(256) int                 g_perm0[K0];
__device__ __align__(256) int                 g_perm1[K1];
__device__ __align__(256) int                 g_perm2[K2];
__device__ __align__(256) int                 g_inv0[N_NODES];
__device__ __align__(256) int                 g_inv1[K0];
__device__ __align__(256) int                 g_inv2[K1];
__device__ __align__(256) float               g_xA[N_NODES * D];
__device__ __align__(256) float               g_xs1[K0 * D];
__device__ __align__(256) float               g_xs2[K1 * D];
__device__ __align__(256) __nv_bfloat16       g_Hg0h[(size_t)K0 * K0];
__device__ __align__(256) __nv_bfloat16       g_Hg0l[(size_t)K0 * K0];
__device__ __align__(256) __nv_bfloat16       g_Hg1h[(size_t)K1 * K1];
__device__ __align__(256) __nv_bfloat16       g_Hg1l[(size_t)K1 * K1];
__device__ __align__(256) __nv_bfloat16       g_Hg2h[(size_t)K2 * K2];
__device__ __align__(256) __nv_bfloat16       g_Hg2l[(size_t)K2 * K2];
__device__ __align__(256) float               g_part[4 * 1024 * 1024];
__device__ __align__(256) __nv_bfloat16       g_yth[D * N_NODES];
__device__ __align__(256) __nv_bfloat16       g_ytl[D * N_NODES];

// ---------------- PTX helpers ----------------
__device__ __forceinline__ uint32_t smem_u32(const void* p) {
    uint32_t a;
    asm("{ .reg .u64 t; cvta.to.shared.u64 t, %1; cvt.u32.u64 %0, t; }" : "=r"(a) : "l"(p));
    return a;
}
__device__ __forceinline__ void cpasync16(uint32_t dst, const void* src) {
    asm volatile("cp.async.cg.shared.global [%0], [%1], 16;" :: "r"(dst), "l"(src));
}
__device__ __forceinline__ void ldsm4(uint32_t* r, uint32_t a) {
    asm volatile("ldmatrix.sync.aligned.m8n8.x4.shared.b16 {%0,%1,%2,%3}, [%4];"
                 : "=r"(r[0]), "=r"(r[1]), "=r"(r[2]), "=r"(r[3]) : "r"(a));
}
__device__ __forceinline__ void mma_bf16(float* c, const uint32_t* a, uint32_t b0, uint32_t b1) {
    asm volatile("mma.sync.aligned.m16n8k16.row.col.f32.bf16.bf16.f32 "
                 "{%0,%1,%2,%3}, {%4,%5,%6,%7}, {%8,%9}, {%0,%1,%2,%3};"
                 : "+f"(c[0]), "+f"(c[1]), "+f"(c[2]), "+f"(c[3])
                 : "r"(a[0]), "r"(a[1]), "r"(a[2]), "r"(a[3]), "r"(b0), "r"(b1));
}
__device__ __forceinline__ uint32_t pack_bf16x2(float a, float b) {
    __nv_bfloat162 t = __floats2bfloat162_rn(a, b);
    return *reinterpret_cast<uint32_t*>(&t);
}
__device__ __forceinline__ unsigned long long score_to_key(float s, int row) {
    unsigned int b = __float_as_uint(s);
    b ^= (b & 0x80000000u) ? 0xFFFFFFFFu : 0x80000000u;
    unsigned int desc = ~b;
    return (((unsigned long long)desc) << 32) | (unsigned int)row;
}
__device__ __forceinline__ uint32_t swz(uint32_t row, uint32_t gran) {
    return row * 64u + ((gran ^ ((row >> 1) & 3u)) * 16u);
}

// ---------------- score + sort key (also resets inv) ----------------
__global__ void score_key_kernel(const float* __restrict__ x, const float* __restrict__ w,
                                 float* __restrict__ score, unsigned long long* __restrict__ key,
                                 int* __restrict__ inv, int n) {
    int warp = threadIdx.x >> 5, lane = threadIdx.x & 31;
    int row = blockIdx.x * (blockDim.x >> 5) + warp;
    if (row >= n) return;
    float4 xv = reinterpret_cast<const float4*>(x + (size_t)row * D)[lane];
    float4 wv = reinterpret_cast<const float4*>(w)[lane];
    float d  = xv.x * wv.x + xv.y * wv.y + xv.z * wv.z + xv.w * wv.w;
    float ww = wv.x * wv.x + wv.y * wv.y + wv.z * wv.z + wv.w * wv.w;
    #pragma unroll
    for (int o = 16; o; o >>= 1) {
        d  += __shfl_xor_sync(0xffffffffu, d, o);
        ww += __shfl_xor_sync(0xffffffffu, ww, o);
    }
    if (lane == 0) {
        float s = tanhf(d / sqrtf(ww));
        score[row] = s;
        key[row] = score_to_key(s, row);
        inv[row] = -1;
    }
}

// ---------------- tiled bitonic sort (R9 proven structure) ----------------
__global__ void sort_local(unsigned long long* __restrict__ key) {
    __shared__ unsigned long long s[SORT_TILE];
    int tid = threadIdx.x;
    int base = blockIdx.x * SORT_TILE;
    s[tid] = key[base + tid];
    s[tid + 1024] = key[base + tid + 1024];
    __syncthreads();
    for (int ksz = 2; ksz <= SORT_TILE; ksz <<= 1) {
        for (int j = ksz >> 1; j > 0; j >>= 1) {
            int i = ((tid & ~(j - 1)) << 1) | (tid & (j - 1));
            int x = i | j;
            bool up = (((base + i) & ksz) == 0);
            unsigned long long a = s[i], b = s[x];
            if ((a > b) == up) { s[i] = b; s[x] = a; }
            if (j > 32 || j == 1) __syncthreads(); else __syncwarp();
        }
    }
    key[base + tid] = s[tid];
    key[base + tid + 1024] = s[tid + 1024];
}

__global__ void lmerge(unsigned long long* __restrict__ key, int ksz) {
    __shared__ unsigned long long s[SORT_TILE];
    int tid = threadIdx.x;
    int base = blockIdx.x * SORT_TILE;
    s[tid] = key[base + tid];
    s[tid + 1024] = key[base + tid + 1024];
    __syncthreads();
    for (int j = SORT_TILE >> 1; j > 0; j >>= 1) {
        int i = ((tid & ~(j - 1)) << 1) | (tid & (j - 1));
        int x = i | j;
        bool up = (((base + i) & ksz) == 0);
        unsigned long long a = s[i], b = s[x];
        if ((a > b) == up) { s[i] = b; s[x] = a; }
        if (j > 32 || j == 1) __syncthreads(); else __syncwarp();
    }
    key[base + tid] = s[tid];
    key[base + tid + 1024] = s[tid + 1024];
}

__global__ void gmerge(unsigned long long* __restrict__ key, int ksz, int j) {
    int p = blockIdx.x * blockDim.x + threadIdx.x;
    int i = ((p & ~(j - 1)) << 1) | (p & (j - 1));
    int x = i | j;
    bool up = ((i & ksz) == 0);
    unsigned long long a = key[i], b = key[x];
    if ((a > b) == up) { key[i] = b; key[x] = a; }
}

__global__ void gmerge2_8192(unsigned long long* __restrict__ key) {
    int q = blockIdx.x * blockDim.x + threadIdx.x;  // 0..2047
    unsigned long long a0 = key[q], a1 = key[q + 2048], a2 = key[q + 4096], a3 = key[q + 6144];
    unsigned long long t;
    if (a0 > a2) { t = a0; a0 = a2; a2 = t; }
    if (a1 > a3) { t = a1; a1 = a3; a3 = t; }
    if (a0 > a1) { t = a0; a0 = a1; a1 = t; }
    if (a2 > a3) { t = a2; a2 = a3; a3 = t; }
    key[q] = a0; key[q + 2048] = a1; key[q + 4096] = a2; key[q + 6144] = a3;
}

static void run_sort(unsigned long long* key, int n) {
    sort_local<<<n / SORT_TILE, 1024>>>(key);
    if (n >= 4096) {
        gmerge<<<n / 512, 256>>>(key, 4096, 2048);
        lmerge<<<n / SORT_TILE, 1024>>>(key, 4096);
    }
    if (n >= 8192) {
        gmerge2_8192<<<8, 256>>>(key);
        lmerge<<<n / SORT_TILE, 1024>>>(key, 8192);
    }
}

// ---------------- gather rows + gate by score, emit perm + inverse ----------------
__global__ void gather_gate_kernel(const float* __restrict__ xin,
                                   const unsigned long long* __restrict__ key,
                                   const float* __restrict__ score,
                                   float* __restrict__ xout, int* __restrict__ perm,
                                   int* __restrict__ inv, int k) {
    int i = blockIdx.x;
    int p = (int)(key[i] & 0xffffffffu);
    if (threadIdx.x == 0) { perm[i] = p; inv[p] = i; }
    float s = score[p];
    xout[(size_t)i * D + threadIdx.x] = xin[(size_t)p * D + threadIdx.x] * s;
}

// ---------------- H[perm][:,perm] -> bf16 hi/lo planes, cp.async double-buffered ----------------
__global__ void gatherH_pipe(const float* __restrict__ H, const int* __restrict__ perm,
                             __nv_bfloat16* __restrict__ Hh, __nv_bfloat16* __restrict__ Hl,
                             int k, int rowW) {
    extern __shared__ float sm[];
    float* buf0 = sm;
    float* buf1 = sm + rowW;
    int* ps = (int*)(sm + 2 * rowW);
    const int tid = threadIdx.x;            // GH_THR
    const int i0 = blockIdx.x * GH_ROWS;
    const int nch = rowW / 4;                // 16B chunks per row

    for (int j = tid; j < k; j += GH_THR) ps[j] = __ldg(&perm[j]);

    // prologue: stage row 0
    {
        int pi = __ldg(&perm[i0]);
        const char* src = (const char*)(H + (size_t)pi * N_NODES);
        uint32_t dst = smem_u32(buf0);
        for (int c = tid; c < nch; c += GH_THR) cpasync16(dst + c * 16u, src + (size_t)c * 16);
        asm volatile("cp.async.commit_group;");
    }

    for (int r = 0; r < GH_ROWS; r++) {
        asm volatile("cp.async.wait_group 0;" ::: "memory");
        __syncthreads();    // row r visible; all threads done gathering row r-1 (frees alt buffer)
        if (r + 1 < GH_ROWS) {
            int pi = __ldg(&perm[i0 + r + 1]);
            const char* src = (const char*)(H + (size_t)pi * N_NODES);
            uint32_t dst = smem_u32(((r + 1) & 1) ? buf1 : buf0);
            for (int c = tid; c < nch; c += GH_THR) cpasync16(dst + c * 16u, src + (size_t)c * 16);
            asm volatile("cp.async.commit_group;");
        }
        const float* rowf = (r & 1) ? buf1 : buf0;
        int i = i0 + r;
        __nv_bfloat16* dh = Hh + (size_t)i * k;
        __nv_bfloat16* dl = Hl + (size_t)i * k;
        for (int j0 = tid * 8; j0 < k; j0 += GH_THR * 8) {
            uint32_t hv[4], lv[4];
            #pragma unroll
            for (int q = 0; q < 4; q++) {
                float v0 = rowf[ps[j0 + 2 * q]];
                float v1 = rowf[ps[j0 + 2 * q + 1]];
                float h0 = __bfloat162float(__float2bfloat16(v0));
                float h1 = __bfloat162float(__float2bfloat16(v1));
                hv[q] = pack_bf16x2(v0, v1);
                lv[q] = pack_bf16x2(v0 - h0, v1 - h1);
            }
            *reinterpret_cast<uint4*>(dh + j0) = make_uint4(hv[0], hv[1], hv[2], hv[3]);
            *reinterpret_cast<uint4*>(dl + j0) = make_uint4(lv[0], lv[1], lv[2], lv[3]);
        }
    }
}

// ---------------- Yt = (X @ W + b)^T as bf16 hi/lo planes [128 x n], vectorized stores ----------------
__global__ void xw_trans_kernel(const float* __restrict__ X, const float* __restrict__ W,
                                const float* __restrict__ b,
                                __nv_bfloat16* __restrict__ Yh, __nv_bfloat16* __restrict__ Yl,
                                int n) {
    __shared__ float xs[16][D];
    int r0 = blockIdx.x * 16;
    int tid = threadIdx.x;
    #pragma unroll
    for (int r = 0; r < 16; r++) xs[r][tid] = X[(size_t)(r0 + r) * D + tid];
    __syncthreads();
    float bv = b[tid];
    float acc[16];
    #pragma unroll
    for (int r = 0; r < 16; r++) acc[r] = bv;
    #pragma unroll 4
    for (int kk = 0; kk < D; kk++) {
        float wv = W[kk * D + tid];
        #pragma unroll
        for (int r = 0; r < 16; r++) acc[r] += xs[r][kk] * wv;
    }
    // pack 16 contiguous bf16 per plane into 2 x uint4 (identical values, vector stores)
    uint32_t hp[8], lp[8];
    #pragma unroll
    for (int q = 0; q < 8; q++) {
        float v0 = acc[2 * q], v1 = acc[2 * q + 1];
        float h0 = __bfloat162float(__float2bfloat16(v0));
        float h1 = __bfloat162float(__float2bfloat16(v1));
        hp[q] = pack_bf16x2(v0, v1);
        lp[q] = pack_bf16x2(v0 - h0, v1 - h1);
    }
    __nv_bfloat16* dh = Yh + (size_t)tid * n + r0;
    __nv_bfloat16* dl = Yl + (size_t)tid * n + r0;
    reinterpret_cast<uint4*>(dh)[0] = make_uint4(hp[0], hp[1], hp[2], hp[3]);
    reinterpret_cast<uint4*>(dh)[1] = make_uint4(hp[4], hp[5], hp[6], hp[7]);
    reinterpret_cast<uint4*>(dl)[0] = make_uint4(lp[0], lp[1], lp[2], lp[3]);
    reinterpret_cast<uint4*>(dl)[1] = make_uint4(lp[4], lp[5], lp[6], lp[7]);
}

// ---------------- mma.sync bf16 3-chain split-K GEMM, 3-stage swizzled pipeline ----------------
template <bool CONV>
__global__ void __launch_bounds__(256, 2)
mma_gemm(const float* __restrict__ Afp,
         const __nv_bfloat16* __restrict__ Ahp, const __nv_bfloat16* __restrict__ Alp,
         const __nv_bfloat16* __restrict__ Bhp, const __nv_bfloat16* __restrict__ Blp,
         float* __restrict__ part, int n, int Kc) {
    extern __shared__ char dyn[];
    uint32_t base = (smem_u32(dyn) + 127) & ~127u;

    const int tid = threadIdx.x, lane = tid & 31, wid = tid >> 5;
    const int warp_m = wid & 3, warp_n = wid >> 2;
    const int rowTile = blockIdx.x * BM;
    const int kbase = blockIdx.y * Kc;
    const int nc = Kc / BK;

    const uint32_t oAh = 0, oAl = TILE_B, oBh = 2 * TILE_B, oBl = 3 * TILE_B;

    const int i0 = tid * 2,       r0 = i0 >> 2, g0 = i0 & 3;
    const int i1 = tid * 2 + 1,   r1 = i1 >> 2, g1 = i1 & 3;
    const uint32_t so0 = swz(r0, g0), so1 = swz(r1, g1);

    const int a_row = tid >> 1;
    const int a_g   = (tid & 1) * 2;
    const uint32_t aso0 = swz(a_row, a_g), aso1 = swz(a_row, a_g + 1);
    float4 av[4];

    auto issue_stage = [&](int c) {
        uint32_t sb = base + (uint32_t)(c % NSTAGE) * STAGE_B;
        int kk = kbase + c * BK;
        cpasync16(sb + oBh + so0, Bhp + (size_t)r0 * n + kk + g0 * 8);
        cpasync16(sb + oBh + so1, Bhp + (size_t)r1 * n + kk + g1 * 8);
        cpasync16(sb + oBl + so0, Blp + (size_t)r0 * n + kk + g0 * 8);
        cpasync16(sb + oBl + so1, Blp + (size_t)r1 * n + kk + g1 * 8);
        if (!CONV) {
            cpasync16(sb + oAh + so0, Ahp + (size_t)(rowTile + r0) * n + kk + g0 * 8);
            cpasync16(sb + oAh + so1, Ahp + (size_t)(rowTile + r1) * n + kk + g1 * 8);
            cpasync16(sb + oAl + so0, Alp + (size_t)(rowTile + r0) * n + kk + g0 * 8);
            cpasync16(sb + oAl + so1, Alp + (size_t)(rowTile + r1) * n + kk + g1 * 8);
        }
        asm volatile("cp.async.commit_group;");
    };
    auto ldg_A = [&](int c) {
        if (CONV) {
            const float4* p = reinterpret_cast<const float4*>(
                Afp + (size_t)(rowTile + a_row) * n + kbase + c * BK + (tid & 1) * 16);
            #pragma unroll
            for (int q = 0; q < 4; q++) av[q] = p[q];
        }
    };
    auto sts_A = [&](int c) {
        if (CONV) {
            uint32_t sb = base + (uint32_t)(c % NSTAGE) * STAGE_B;
            uint32_t h[8], l[8];
            #pragma unroll
            for (int q = 0; q < 4; q++) {
                const float4 v = av[q];
                float hx = __bfloat162float(__float2bfloat16(v.x));
                float hy = __bfloat162float(__float2bfloat16(v.y));
                float hz = __bfloat162float(__float2bfloat16(v.z));
                float hw = __bfloat162float(__float2bfloat16(v.w));
                h[q * 2]     = pack_bf16x2(v.x, v.y);
                h[q * 2 + 1] = pack_bf16x2(v.z, v.w);
                l[q * 2]     = pack_bf16x2(v.x - hx, v.y - hy);
                l[q * 2 + 1] = pack_bf16x2(v.z - hz, v.w - hw);
            }
            asm volatile("st.shared.v4.b32 [%0], {%1,%2,%3,%4};"
                         :: "r"(sb + oAh + aso0), "r"(h[0]), "r"(h[1]), "r"(h[2]), "r"(h[3]));
            asm volatile("st.shared.v4.b32 [%0], {%1,%2,%3,%4};"
                         :: "r"(sb + oAh + aso1), "r"(h[4]), "r"(h[5]), "r"(h[6]), "r"(h[7]));
            asm volatile("st.shared.v4.b32 [%0], {%1,%2,%3,%4};"
                         :: "r"(sb + oAl + aso0), "r"(l[0]), "r"(l[1]), "r"(l[2]), "r"(l[3]));
            asm volatile("st.shared.v4.b32 [%0], {%1,%2,%3,%4};"
                         :: "r"(sb + oAl + aso1), "r"(l[4]), "r"(l[5]), "r"(l[6]), "r"(l[7]));
        }
    };

    float acc[2][8][4];
    #pragma unroll
    for (int i = 0; i < 2; i++)
        #pragma unroll
        for (int j = 0; j < 8; j++)
            #pragma unroll
            for (int q = 0; q < 4; q++) acc[i][j][q] = 0.f;

    const int lr = lane & 7, lsel = lane >> 3;

    issue_stage(0);
    if (CONV) { ldg_A(0); sts_A(0); }
    if (nc > 1) {
        issue_stage(1);
        if (CONV) { ldg_A(1); sts_A(1); }
    }

    for (int c = 0; c < nc; c++) {
        uint32_t sb = base + (uint32_t)(c % NSTAGE) * STAGE_B;
        if (c + 1 < nc) asm volatile("cp.async.wait_group 1;" ::: "memory");
        else            asm volatile("cp.async.wait_group 0;" ::: "memory");
        __syncthreads();

        bool pf = (c + 2 < nc);
        if (pf) { issue_stage(c + 2); ldg_A(c + 2); }

        #pragma unroll
        for (int ks = 0; ks < 2; ks++) {
            uint32_t Ahf[2][4], Alf[2][4];
            #pragma unroll
            for (int mf = 0; mf < 2; mf++) {
                uint32_t row = warp_m * 32 + mf * 16 + lr + (lsel & 1) * 8;
                uint32_t gr  = ks * 2 + (lsel >> 1);
                uint32_t off = swz(row, gr);
                ldsm4(Ahf[mf], sb + oAh + off);
                ldsm4(Alf[mf], sb + oAl + off);
            }
            #pragma unroll
            for (int p = 0; p < 4; p++) {
                uint32_t Bhf[4], Blf[4];
                uint32_t row = warp_n * 64 + p * 16 + lr + (lsel >> 1) * 8;
                uint32_t gr  = ks * 2 + (lsel & 1);
                uint32_t off = swz(row, gr);
                ldsm4(Bhf, sb + oBh + off);
                ldsm4(Blf, sb + oBl + off);
                #pragma unroll
                for (int mf = 0; mf < 2; mf++)
                    #pragma unroll
                    for (int s = 0; s < 2; s++) {
                        int nf = p * 2 + s;
                        mma_bf16(acc[mf][nf], Ahf[mf], Bhf[s * 2], Bhf[s * 2 + 1]);
                        mma_bf16(acc[mf][nf], Ahf[mf], Blf[s * 2], Blf[s * 2 + 1]);
                        mma_bf16(acc[mf][nf], Alf[mf], Bhf[s * 2], Bhf[s * 2 + 1]);
                    }
            }
        }
        if (pf) sts_A(c + 2);
    }

    float* Zp = part + (size_t)blockIdx.y * n * D;
    const int g = lane >> 2, cq = (lane & 3) * 2;
    #pragma unroll
    for (int mf = 0; mf < 2; mf++) {
        int row = rowTile + warp_m * 32 + mf * 16 + g;
        #pragma unroll
        for (int nf = 0; nf < 8; nf++) {
            int col = warp_n * 64 + nf * 8 + cq;
            *reinterpret_cast<float2*>(&Zp[(size_t)row * D + col]) =
                make_float2(acc[mf][nf][0], acc[mf][nf][1]);
            *reinterpret_cast<float2*>(&Zp[(size_t)(row + 8) * D + col]) =
                make_float2(acc[mf][nf][2], acc[mf][nf][3]);
        }
    }
}

// ---------------- deterministic partial reduction + relu (float4) ----------------
__global__ void reduce_relu_kernel(const float* __restrict__ Zpart, float* __restrict__ Z,
                                   int total4, int SK) {
    int i = blockIdx.x * blockDim.x + threadIdx.x;
    if (i >= total4) return;
    float4 s = make_float4(0.f, 0.f, 0.f, 0.f);
    for (int p = 0; p < SK; p++) {
        float4 v = reinterpret_cast<const float4*>(Zpart)[(size_t)p * total4 + i];
        s.x += v.x; s.y += v.y; s.z += v.z; s.w += v.w;
    }
    s.x = fmaxf(s.x, 0.f); s.y = fmaxf(s.y, 0.f);
    s.z = fmaxf(s.z, 0.f); s.w = fmaxf(s.w, 0.f);
    reinterpret_cast<float4*>(Z)[i] = s;
}

// ---------------- fused: partial reduction + relu + next-level score/key + inv reset ----------------
__global__ void reduce_relu_score_kernel(const float* __restrict__ Zpart, float* __restrict__ Z,
                                         int n, int SK, const float* __restrict__ w,
                                         float* __restrict__ score,
                                         unsigned long long* __restrict__ key,
                                         int* __restrict__ inv) {
    int r = blockIdx.x, t = threadIdx.x;
    float s = 0.f;
    for (int p = 0; p < SK; p++) s += Zpart[((size_t)p * n + r) * D + t];
    s = fmaxf(s, 0.f);
    Z[(size_t)r * D + t] = s;
    float wv = w[t];
    float d = s * wv, ww = wv * wv;
    #pragma unroll
    for (int o = 16; o; o >>= 1) {
        d  += __shfl_xor_sync(0xffffffffu, d, o);
        ww += __shfl_xor_sync(0xffffffffu, ww, o);
    }
    __shared__ float sd[4], sw[4];
    int warp = t >> 5, lane = t & 31;
    if (lane == 0) { sd[warp] = d; sw[warp] = ww; }
    __syncthreads();
    if (t == 0) {
        float dd  = sd[0] + sd[1] + sd[2] + sd[3];
        float www = sw[0] + sw[1] + sw[2] + sw[3];
        float sc = tanhf(dd / sqrtf(www));
        score[r] = sc;
        key[r] = score_to_key(sc, r);
        inv[r] = -1;
    }
}

// ---------------- fused UP entry: xA[r] = res[r] + (inv[r]>=0 ? relu(sum_p part[p][inv[r]]) : 0)
__global__ void up_reduce_combine_kernel(const float* __restrict__ Zpart, int kprev, int SK,
                                         const float* __restrict__ res, const int* __restrict__ inv,
                                         float* __restrict__ dst) {
    int r = blockIdx.x, t = threadIdx.x;
    float v = res[(size_t)r * D + t];
    int i = __ldg(&inv[r]);
    if (i >= 0) {
        float s = 0.f;
        for (int p = 0; p < SK; p++)
            s += Zpart[((size_t)p * kprev + i) * D + t];
        v += fmaxf(s, 0.f);
    }
    dst[(size_t)r * D + t] = v;
}

// ---------------- host orchestration (R9 S values: 256 CTAs per GEMM) ----------------
static inline int pick_sk(int n) {
    if (n >= 8192) return 4;
    if (n >= 4096) return 8;
    if (n >= 2048) return 16;
    return 32;
}

extern "C" void kernel_launch(void* const* d_in, const int* in_sizes, int n_in,
                              void* d_out, int out_size) {
    const float* feat = (const float*)d_in[0];
    const float* H    = (const float*)d_in[1];
    const float* pw[3] = {(const float*)d_in[2], (const float*)d_in[3], (const float*)d_in[4]};
    const float* Wd[3] = {(const float*)d_in[5], (const float*)d_in[7], (const float*)d_in[9]};
    const float* bd[3] = {(const float*)d_in[6], (const float*)d_in[8], (const float*)d_in[10]};
    const float* Wu[3] = {(const float*)d_in[11], (const float*)d_in[13], (const float*)d_in[15]};
    const float* bu[3] = {(const float*)d_in[12], (const float*)d_in[14], (const float*)d_in[16]};
    float* out = (float*)d_out;

    float *score, *xA, *xs1, *xs2, *part;
    unsigned long long* key;
    int *perm0, *perm1, *perm2, *inv0, *inv1, *inv2;
    __nv_bfloat16 *yth, *ytl, *Hg0h, *Hg0l, *Hg1h, *Hg1l, *Hg2h, *Hg2l;
    cudaGetSymbolAddress((void**)&score, g_score);
    cudaGetSymbolAddress((void**)&key,   g_key);
    cudaGetSymbolAddress((void**)&perm0, g_perm0);
    cudaGetSymbolAddress((void**)&perm1, g_perm1);
    cudaGetSymbolAddress((void**)&perm2, g_perm2);
    cudaGetSymbolAddress((void**)&inv0,  g_inv0);
    cudaGetSymbolAddress((void**)&inv1,  g_inv1);
    cudaGetSymbolAddress((void**)&inv2,  g_inv2);
    cudaGetSymbolAddress((void**)&xA,    g_xA);
    cudaGetSymbolAddress((void**)&xs1,   g_xs1);
    cudaGetSymbolAddress((void**)&xs2,   g_xs2);
    cudaGetSymbolAddress((void**)&part,  g_part);
    cudaGetSymbolAddress((void**)&yth,   g_yth);
    cudaGetSymbolAddress((void**)&ytl,   g_ytl);
    cudaGetSymbolAddress((void**)&Hg0h,  g_Hg0h);
    cudaGetSymbolAddress((void**)&Hg0l,  g_Hg0l);
    cudaGetSymbolAddress((void**)&Hg1h,  g_Hg1h);
    cudaGetSymbolAddress((void**)&Hg1l,  g_Hg1l);
    cudaGetSymbolAddress((void**)&Hg2h,  g_Hg2h);
    cudaGetSymbolAddress((void**)&Hg2l,  g_Hg2l);

    cudaFuncSetAttribute(gatherH_pipe,    cudaFuncAttributeMaxDynamicSharedMemorySize, 98304);
    cudaFuncSetAttribute(mma_gemm<true>,  cudaFuncAttributeMaxDynamicSharedMemorySize, GEMM_DYN);
    cudaFuncSetAttribute(mma_gemm<false>, cudaFuncAttributeMaxDynamicSharedMemorySize, GEMM_DYN);

    int S;

    // ---------------- DOWN level 0 : n=8192 -> k=4096 ----------------
    score_key_kernel<<<N_NODES / 4, 128>>>(feat, pw[0], score, key, inv0, N_NODES);
    run_sort(key, N_NODES);
    gather_gate_kernel<<<K0, 128>>>(feat, key, score, xA, perm0, inv0, K0);
    gatherH_pipe<<<K0 / GH_ROWS, GH_THR, (2 * N_NODES + K0) * 4>>>(H, perm0, Hg0h, Hg0l, K0, N_NODES);
    xw_trans_kernel<<<K0 / 16, 128>>>(xA, Wd[0], bd[0], yth, ytl, K0);
    S = pick_sk(K0);
    mma_gemm<false><<<dim3(K0 / BM, S), 256, GEMM_DYN>>>(nullptr, Hg0h, Hg0l, yth, ytl, part, K0, K0 / S);
    reduce_relu_score_kernel<<<K0, 128>>>(part, xs1, K0, S, pw[1], score, key, inv1);

    // ---------------- DOWN level 1 : n=4096 -> k=2048 ----------------
    run_sort(key, K0);
    gather_gate_kernel<<<K1, 128>>>(xs1, key, score, xA, perm1, inv1, K1);
    gatherH_pipe<<<K1 / GH_ROWS, GH_THR, (2 * K0 + K1) * 4>>>(H, perm1, Hg1h, Hg1l, K1, K0);  // cols < 4096 (bug preserved)
    xw_trans_kernel<<<K1 / 16, 128>>>(xA, Wd[1], bd[1], yth, ytl, K1);
    S = pick_sk(K1);
    mma_gemm<false><<<dim3(K1 / BM, S), 256, GEMM_DYN>>>(nullptr, Hg1h, Hg1l, yth, ytl, part, K1, K1 / S);
    reduce_relu_score_kernel<<<K1, 128>>>(part, xs2, K1, S, pw[2], score, key, inv2);

    // ---------------- DOWN level 2 : n=2048 -> k=1024 ----------------
    run_sort(key, K1);
    gather_gate_kernel<<<K2, 128>>>(xs2, key, score, xA, perm2, inv2, K2);
    gatherH_pipe<<<K2 / GH_ROWS, GH_THR, (2 * K1 + K2) * 4>>>(H, perm2, Hg2h, Hg2l, K2, K1);  // cols < 2048
    xw_trans_kernel<<<K2 / 16, 128>>>(xA, Wd[2], bd[2], yth, ytl, K2);
    S = pick_sk(K2);
    mma_gemm<false><<<dim3(K2 / BM, S), 256, GEMM_DYN>>>(nullptr, Hg2h, Hg2l, yth, ytl, part, K2, K2 / S);
    int S_d2 = S;

    // ---------------- UP i=0 (j=2): res=xs2(2048), graph=Hg1, inv2 ----------------
    up_reduce_combine_kernel<<<K1, 128>>>(part, K2, S_d2, xs2, inv2, xA);
    xw_trans_kernel<<<K1 / 16, 128>>>(xA, Wu[0], bu[0], yth, ytl, K1);
    S = pick_sk(K1);
    mma_gemm<false><<<dim3(K1 / BM, S), 256, GEMM_DYN>>>(nullptr, Hg1h, Hg1l, yth, ytl, part, K1, K1 / S);
    int S_u0 = S;

    // ---------------- UP i=1 (j=1): res=xs1(4096), graph=Hg0, inv1 ----------------
    up_reduce_combine_kernel<<<K0, 128>>>(part, K1, S_u0, xs1, inv1, xA);
    xw_trans_kernel<<<K0 / 16, 128>>>(xA, Wu[1], bu[1], yth, ytl, K0);
    S = pick_sk(K0);
    mma_gemm<false><<<dim3(K0 / BM, S), 256, GEMM_DYN>>>(nullptr, Hg0h, Hg0l, yth, ytl, part, K0, K0 / S);
    int S_u1 = S;

    // ---------------- UP i=2 (j=0): res=feat(8192), graph=H (fp32, convert), inv0 ----------------
    up_reduce_combine_kernel<<<N_NODES, 128>>>(part, K0, S_u1, feat, inv0, xA);
    xw_trans_kernel<<<N_NODES / 16, 128>>>(xA, Wu[2], bu[2], yth, ytl, N_NODES);
    S = pick_sk(N_NODES);
    mma_gemm<true><<<dim3(N_NODES / BM, S), 256, GEMM_DYN>>>(H, nullptr, nullptr, yth, ytl, part, N_NODES, N_NODES / S);
    reduce_relu_kernel<<<(N_NODES * D / 4 + 255) / 256, 256>>>(part, out, N_NODES * D / 4, S);
}